// round 2
// baseline (speedup 1.0000x reference)
#include <cuda_runtime.h>

#define TT   65536
#define SD   100
#define HID  8
#define NOBS 12
#define DTC  0.01f

__device__ __forceinline__ unsigned long long pack2(float lo, float hi) {
    unsigned long long r;
    asm("mov.b64 %0, {%1, %2};" : "=l"(r) : "f"(lo), "f"(hi));
    return r;
}
__device__ __forceinline__ void unpack2(unsigned long long v, float& lo, float& hi) {
    asm("mov.b64 {%0, %1}, %2;" : "=f"(lo), "=f"(hi) : "l"(v));
}
__device__ __forceinline__ void fma2(unsigned long long& acc, unsigned long long a, unsigned long long b) {
    asm("fma.rn.f32x2 %0, %1, %2, %0;" : "+l"(acc) : "l"(a), "l"(b));
}
__device__ __forceinline__ void add2(unsigned long long& acc, unsigned long long b) {
    asm("add.rn.f32x2 %0, %0, %1;" : "+l"(acc) : "l"(b));
}

__global__ void __launch_bounds__(256, 1) greybox_kernel(
    const float* __restrict__ c0,
    const float* __restrict__ w,
    const float* __restrict__ u,
    const float* __restrict__ A,
    const float* __restrict__ Bw,
    const float* __restrict__ W1,
    const float* __restrict__ b1,
    const float* __restrict__ W2,
    const float* __restrict__ b2,
    const int*   __restrict__ obs,
    float* __restrict__ outc,
    float* __restrict__ outy)
{
    // ping-pong state buffers: g (100 + 4 zero pad), h (8)
    __shared__ __align__(16) float gbuf[2][104];
    __shared__ __align__(16) float hbuf[2][8];
    __shared__ __align__(16) float w2s[SD * HID];   // W2 staging (setup only)

    const int tid = threadIdx.x;
    const bool isA   = (tid < SD);                      // state rows 0..99
    const bool isZ   = (tid >= 104 && tid < 112);       // hidden rows 0..7
    const bool isCmp = (tid < 128);                     // compute warps 0-3
    const bool isOC  = (tid >= 128 && tid < 128 + SD);  // outc emitters
    const bool isOY  = (tid >= 228 && tid < 228 + NOBS);// outy emitters
    const int arow = tid;
    const int zrow = tid - 104;

    // ---- one-time setup ----
    for (int i = tid; i < SD * HID; i += 256) w2s[i] = W2[i];
    if (tid < 104) { gbuf[0][tid] = 0.f; gbuf[1][tid] = 0.f; }
    if (tid < 8)   { hbuf[0][tid] = 0.f; hbuf[1][tid] = 0.f; }
    __syncthreads();

    // compute-lane row data
    unsigned long long rva[52];
    unsigned long long mrow[4] = {0ull, 0ull, 0ull, 0ull};
    float bw0 = 0.f, bw1 = 0.f, gc = 0.f;

    // output-lane row data
    unsigned long long w2d[4] = {0ull, 0ull, 0ull, 0ull};
    float cb = 0.f;
    int orow = 0;

    if (isCmp) {
#pragma unroll
        for (int k = 0; k < 52; k++) rva[k] = 0ull;
        if (isA || isZ) {
            const float* Rr = isA ? (A + arow * SD) : (W1 + zrow * SD);
#pragma unroll
            for (int k = 0; k < 50; k++) rva[k] = pack2(Rr[2 * k], Rr[2 * k + 1]);
            float m[8]; float s = 0.f;
#pragma unroll
            for (int j = 0; j < 8; j++) m[j] = 0.f;
            for (int k = 0; k < SD; k++) {
                float a = Rr[k];
#pragma unroll
                for (int j = 0; j < 8; j++) m[j] += a * w2s[k * HID + j];
                s += a * b2[k];
            }
#pragma unroll
            for (int j = 0; j < 4; j++) mrow[j] = pack2(DTC * m[2 * j], DTC * m[2 * j + 1]);
            if (isA) {
                gc = DTC * s;
                bw0 = Bw[arow * 2];
                bw1 = Bw[arow * 2 + 1];
            } else {
                gc = b1[zrow] + DTC * s;  // zc
            }
        }
    } else {
        if (isOC) orow = tid - 128;
        else if (isOY) orow = obs[tid - 228];
        if (isOC || isOY) {
#pragma unroll
            for (int j = 0; j < 4; j++)
                w2d[j] = pack2(DTC * w2s[orow * HID + 2 * j], DTC * w2s[orow * HID + 2 * j + 1]);
            cb = DTC * b2[orow];
        }
    }

    // initial state: h_0 = 0, g_0 = c0 - dt*b2  (so c_0 = g_0 + dt*(W2 h_0 + b2) = c0)
    if (isA) gbuf[0][arow] = c0[arow] - DTC * b2[arow];
    __syncthreads();

    // prefetch depth 2: values for iterations k and k+1 live in registers
    float u_c = 0.f, u_n = 0.f;
    float2 w_c = make_float2(0.f, 0.f), w_n = make_float2(0.f, 0.f);
    if (isA) { u_c = u[arow]; u_n = u[SD + arow]; }
    if (isCmp) {
        const float2* wp = reinterpret_cast<const float2*>(w);
        w_c = wp[0]; w_n = wp[1];
    }

    int p = 0;
    for (int k = 0; k < TT; k++) {
        // issue loads for iteration k+2 (consumed 2 steps later -> L2 latency hidden)
        const int kn = (k + 2 < TT) ? (k + 2) : (TT - 1);
        float u_n2 = 0.f;
        float2 w_n2 = w_n;
        if (isA) u_n2 = __ldcg(&u[(size_t)kn * SD + arow]);
        if (isCmp) w_n2 = __ldcg(reinterpret_cast<const float2*>(w) + kn);

        if (isCmp) {
            // ---- advance state: dot(row, g_k) + M.h_k ----
            const unsigned long long* hp = reinterpret_cast<const unsigned long long*>(hbuf[p]);
            unsigned long long h0 = hp[0], h1 = hp[1], h2 = hp[2], h3 = hp[3];

            unsigned long long a0 = 0ull, a1 = 0ull, a2 = 0ull, a3 = 0ull;
            const ulonglong2* gp2 = reinterpret_cast<const ulonglong2*>(gbuf[p]);
#pragma unroll
            for (int q = 0; q < 26; q++) {
                ulonglong2 gg = gp2[q];
                if (q & 1) { fma2(a2, rva[2 * q], gg.x); fma2(a3, rva[2 * q + 1], gg.y); }
                else       { fma2(a0, rva[2 * q], gg.x); fma2(a1, rva[2 * q + 1], gg.y); }
            }
            fma2(a0, mrow[0], h0); fma2(a1, mrow[1], h1);
            fma2(a2, mrow[2], h2); fma2(a3, mrow[3], h3);
            add2(a0, a1); add2(a2, a3); add2(a0, a2);
            float lo, hi; unpack2(a0, lo, hi);
            float dot = lo + hi;

            if (isA) {
                float gn = fmaf(bw0, w_c.x, fmaf(bw1, w_c.y, dot + gc + u_c));
                gbuf[p ^ 1][arow] = gn;
            } else if (isZ) {
                hbuf[p ^ 1][zrow] = tanhf(dot + gc);
            }
        } else if (k > 0 && (isOC || isOY)) {
            // ---- emit state k (buffer p is stable during this iteration) ----
            const unsigned long long* hp = reinterpret_cast<const unsigned long long*>(hbuf[p]);
            unsigned long long cacc = 0ull;
            fma2(cacc, w2d[0], hp[0]); fma2(cacc, w2d[1], hp[1]);
            fma2(cacc, w2d[2], hp[2]); fma2(cacc, w2d[3], hp[3]);
            float lo, hi; unpack2(cacc, lo, hi);
            float cv = gbuf[p][orow] + cb + lo + hi;
            if (isOC) outc[(size_t)(k - 1) * SD + (tid - 128)] = cv;
            else      outy[(size_t)(k - 1) * NOBS + (tid - 228)] = cv;
        }

        u_c = u_n; u_n = u_n2;
        w_c = w_n; w_n = w_n2;
        __syncthreads();
        p ^= 1;
    }

    // ---- epilogue: emit final state TT ----
    if (isOC || isOY) {
        const unsigned long long* hp = reinterpret_cast<const unsigned long long*>(hbuf[p]);
        unsigned long long cacc = 0ull;
        fma2(cacc, w2d[0], hp[0]); fma2(cacc, w2d[1], hp[1]);
        fma2(cacc, w2d[2], hp[2]); fma2(cacc, w2d[3], hp[3]);
        float lo, hi; unpack2(cacc, lo, hi);
        float cv = gbuf[p][orow] + cb + lo + hi;
        if (isOC) outc[(size_t)(TT - 1) * SD + (tid - 128)] = cv;
        else      outy[(size_t)(TT - 1) * NOBS + (tid - 228)] = cv;
    }
}

extern "C" void kernel_launch(void* const* d_in, const int* in_sizes, int n_in,
                              void* d_out, int out_size) {
    const float* c0  = (const float*)d_in[0];
    const float* w   = (const float*)d_in[1];
    const float* u   = (const float*)d_in[2];
    const float* A   = (const float*)d_in[3];
    const float* Bw  = (const float*)d_in[4];
    const float* W1  = (const float*)d_in[5];
    const float* b1  = (const float*)d_in[6];
    const float* W2  = (const float*)d_in[7];
    const float* b2  = (const float*)d_in[8];
    const int*   ob  = (const int*)d_in[9];

    float* outc = (float*)d_out;                      // (T, 100)
    float* outy = (float*)d_out + (size_t)TT * SD;    // (T, 12)

    greybox_kernel<<<1, 256>>>(c0, w, u, A, Bw, W1, b1, W2, b2, ob, outc, outy);
}

// round 3
// speedup vs baseline: 2.0086x; 2.0086x over previous
#include <cuda_runtime.h>

#define TT   65536
#define SD   100
#define HID  8
#define NOBS 12
#define DTC  0.01f

__device__ __forceinline__ unsigned long long pack2(float lo, float hi) {
    unsigned long long r;
    asm("mov.b64 %0, {%1, %2};" : "=l"(r) : "f"(lo), "f"(hi));
    return r;
}
__device__ __forceinline__ void unpack2(unsigned long long v, float& lo, float& hi) {
    asm("mov.b64 {%0, %1}, %2;" : "=f"(lo), "=f"(hi) : "l"(v));
}
__device__ __forceinline__ void fma2(unsigned long long& acc, unsigned long long a, unsigned long long b) {
    asm("fma.rn.f32x2 %0, %1, %2, %0;" : "+l"(acc) : "l"(a), "l"(b));
}
__device__ __forceinline__ void add2(unsigned long long& acc, unsigned long long b) {
    asm("add.rn.f32x2 %0, %0, %1;" : "+l"(acc) : "l"(b));
}
__device__ __forceinline__ float tanh_hw(float x) {
    float r;
    asm("tanh.approx.f32 %0, %1;" : "=f"(r) : "f"(x));
    return r;
}

// ============================================================================
// Kernel 1: the serial rollout. 1 block, 128 threads (4 warps, 1/SMSP).
// State substitution: c_t = g_t + dt*(W2 h_t), with
//   g_{t+1} = A g_t + dt*(A W2) h_t + Bw w_{t+1} + u_{t+1} + dt*b2
//   h_{t+1} = tanh(W1 g_t + dt*(W1 W2) h_t + b1)
//   g_0 = c0, h_0 = 0
// One __syncthreads per step. Emits only outc; y gathered by kernel 2.
// ============================================================================
__global__ void __launch_bounds__(128, 1) greybox_kernel(
    const float* __restrict__ c0,
    const float* __restrict__ w,
    const float* __restrict__ u,
    const float* __restrict__ A,
    const float* __restrict__ Bw,
    const float* __restrict__ W1,
    const float* __restrict__ b1,
    const float* __restrict__ W2,
    const float* __restrict__ b2,
    float* __restrict__ outc)
{
    __shared__ __align__(16) float gbuf[2][104];
    __shared__ __align__(16) float hbuf[2][8];
    __shared__ __align__(16) float w2s[SD * HID];

    const int tid = threadIdx.x;
    const bool isA = (tid < SD);
    const bool isZ = (tid >= 104 && tid < 112);
    const int arow = tid;
    const int zrow = tid - 104;

    // ---- setup ----
    for (int i = tid; i < SD * HID; i += 128) w2s[i] = W2[i];
    if (tid < 104) { gbuf[0][tid] = 0.f; gbuf[1][tid] = 0.f; }
    if (tid < 8)   { hbuf[0][tid] = 0.f; hbuf[1][tid] = 0.f; }
    __syncthreads();

    unsigned long long rva[52];
#pragma unroll
    for (int k = 0; k < 52; k++) rva[k] = 0ull;
    unsigned long long mrow[4] = {0ull, 0ull, 0ull, 0ull};   // dt*(A@W2) or dt*(W1@W2) row
    unsigned long long w2d[4]  = {0ull, 0ull, 0ull, 0ull};   // dt*W2 row (emit)
    float bw0 = 0.f, bw1 = 0.f, gc = 0.f;

    if (isA || isZ) {
        const float* Rr = isA ? (A + arow * SD) : (W1 + zrow * SD);
#pragma unroll
        for (int k = 0; k < 50; k++) rva[k] = pack2(Rr[2 * k], Rr[2 * k + 1]);
        float m[8];
#pragma unroll
        for (int j = 0; j < 8; j++) m[j] = 0.f;
        for (int k = 0; k < SD; k++) {
            float a = Rr[k];
#pragma unroll
            for (int j = 0; j < 8; j++) m[j] += a * w2s[k * HID + j];
        }
#pragma unroll
        for (int j = 0; j < 4; j++) mrow[j] = pack2(DTC * m[2 * j], DTC * m[2 * j + 1]);
        if (isA) {
            gc  = DTC * b2[arow];
            bw0 = Bw[arow * 2];
            bw1 = Bw[arow * 2 + 1];
#pragma unroll
            for (int j = 0; j < 4; j++)
                w2d[j] = pack2(DTC * w2s[arow * HID + 2 * j], DTC * w2s[arow * HID + 2 * j + 1]);
        } else {
            gc = b1[zrow];
        }
    }

    float g_own = 0.f;
    if (isA) { g_own = c0[arow]; gbuf[0][arow] = g_own; }
    __syncthreads();

    // depth-2 prefetch: registers hold inputs for iterations k and k+1
    float u_c = 0.f, u_n = 0.f;
    float2 w_c = make_float2(0.f, 0.f), w_n = make_float2(0.f, 0.f);
    if (isA) { u_c = u[arow]; u_n = u[SD + arow]; }
    {
        const float2* wp = reinterpret_cast<const float2*>(w);
        w_c = wp[0]; w_n = wp[1];
    }

    int p = 0;
    for (int k = 0; k < TT; k++) {
        // prefetch for iteration k+2 (~2 steps of slack covers L2 latency)
        const int kn = (k + 2 < TT) ? (k + 2) : (TT - 1);
        float u_n2 = 0.f;
        if (isA) u_n2 = __ldcg(&u[(size_t)kn * SD + arow]);
        float2 w_n2 = __ldcg(reinterpret_cast<const float2*>(w) + kn);

        // current h (state k)
        const ulonglong2* hp2 = reinterpret_cast<const ulonglong2*>(hbuf[p]);
        ulonglong2 H0 = hp2[0], H1 = hp2[1];

        // ---- emit c_k (k >= 1): c = g + dt*W2 h ----
        if (k > 0 && isA) {
            unsigned long long cacc = 0ull;
            fma2(cacc, w2d[0], H0.x); fma2(cacc, w2d[1], H0.y);
            fma2(cacc, w2d[2], H1.x); fma2(cacc, w2d[3], H1.y);
            float lo, hi; unpack2(cacc, lo, hi);
            outc[(size_t)(k - 1) * SD + arow] = g_own + lo + hi;
        }

        // ---- advance: dot(row, g_k) + mrow.h_k ----
        unsigned long long a0 = 0ull, a1 = 0ull, a2 = 0ull, a3 = 0ull;
        const ulonglong2* gp2 = reinterpret_cast<const ulonglong2*>(gbuf[p]);
#pragma unroll
        for (int q = 0; q < 26; q++) {
            ulonglong2 gg = gp2[q];
            if (q & 1) { fma2(a2, rva[2 * q], gg.x); fma2(a3, rva[2 * q + 1], gg.y); }
            else       { fma2(a0, rva[2 * q], gg.x); fma2(a1, rva[2 * q + 1], gg.y); }
        }
        fma2(a0, mrow[0], H0.x); fma2(a1, mrow[1], H0.y);
        fma2(a2, mrow[2], H1.x); fma2(a3, mrow[3], H1.y);
        add2(a0, a1); add2(a2, a3); add2(a0, a2);
        float lo, hi; unpack2(a0, lo, hi);
        float dot = lo + hi;

        if (isA) {
            float gn = fmaf(bw0, w_c.x, fmaf(bw1, w_c.y, dot + gc + u_c));
            gbuf[p ^ 1][arow] = gn;
            g_own = gn;
        } else if (isZ) {
            hbuf[p ^ 1][zrow] = tanh_hw(dot + gc);
        }

        u_c = u_n; u_n = u_n2;
        w_c = w_n; w_n = w_n2;
        __syncthreads();
        p ^= 1;
    }

    // ---- epilogue: emit state TT ----
    if (isA) {
        const ulonglong2* hp2 = reinterpret_cast<const ulonglong2*>(hbuf[p]);
        ulonglong2 H0 = hp2[0], H1 = hp2[1];
        unsigned long long cacc = 0ull;
        fma2(cacc, w2d[0], H0.x); fma2(cacc, w2d[1], H0.y);
        fma2(cacc, w2d[2], H1.x); fma2(cacc, w2d[3], H1.y);
        float lo, hi; unpack2(cacc, lo, hi);
        outc[(size_t)(TT - 1) * SD + arow] = g_own + lo + hi;
    }
}

// ============================================================================
// Kernel 2: y gather — outy[t, q] = outc[t, obs[q]]. Full-chip, ~15us.
// ============================================================================
__global__ void gather_y_kernel(const float* __restrict__ outc,
                                const int* __restrict__ obs,
                                float* __restrict__ outy)
{
    __shared__ int so[NOBS];
    if (threadIdx.x < NOBS) so[threadIdx.x] = obs[threadIdx.x];
    __syncthreads();

    int t = blockIdx.x * blockDim.x + threadIdx.x;
    if (t >= TT) return;
    const float* row = outc + (size_t)t * SD;
    float* yrow = outy + (size_t)t * NOBS;
#pragma unroll
    for (int q = 0; q < NOBS; q++) yrow[q] = row[so[q]];
}

extern "C" void kernel_launch(void* const* d_in, const int* in_sizes, int n_in,
                              void* d_out, int out_size) {
    const float* c0  = (const float*)d_in[0];
    const float* w   = (const float*)d_in[1];
    const float* u   = (const float*)d_in[2];
    const float* A   = (const float*)d_in[3];
    const float* Bw  = (const float*)d_in[4];
    const float* W1  = (const float*)d_in[5];
    const float* b1  = (const float*)d_in[6];
    const float* W2  = (const float*)d_in[7];
    const float* b2  = (const float*)d_in[8];
    const int*   ob  = (const int*)d_in[9];

    float* outc = (float*)d_out;                      // (T, 100)
    float* outy = (float*)d_out + (size_t)TT * SD;    // (T, 12)

    greybox_kernel<<<1, 128>>>(c0, w, u, A, Bw, W1, b1, W2, b2, outc);
    gather_y_kernel<<<(TT + 255) / 256, 256>>>(outc, ob, outy);
}